// round 2
// baseline (speedup 1.0000x reference)
#include <cuda_runtime.h>
#include <cuda_bf16.h>

constexpr int TIMESTEPS = 1000;
constexpr int B = 4;
constexpr int N = 2048;                                // power of two
constexpr long long E = (long long)N * (N - 1) / 2;    // 2,096,128
constexpr int NBLK = B * (N / 2);                      // 4096 blocks
constexpr int NTHR = 256;

// Cross-block reduction scratch. g_count self-resets (atomicInc wrap), so the
// kernel is graph-replay safe with no host-side zeroing.
__device__ float        g_partials[NBLK];
__device__ unsigned int g_count = 0;

struct Consts { float flip_t, omt, flip_p, omp, r_omt, r_flip; };

// Per-element loss term. Branch-free selects; no division (reciprocals of the
// two possible evidence values are precomputed); fast softplus via MUFU.
__device__ __forceinline__ float term(int a, float uu, float x, const Consts& c) {
    bool  ab    = (a != 0);
    float pa    = ab ? c.omt : c.flip_t;       // Qt[t][a, 1]
    bool  x1    = uu < pa;                     // sampled bit
    float lik   = x1 ? 0.99f : 0.01f;          // Qt[0][x1, 1]
    float prior = ab ? c.omp : c.flip_p;       // Qt[t-1][a, 1]
    float er    = (ab == x1) ? c.r_omt : c.r_flip;  // 1 / Qt[t][a, x1]
    float qt    = lik * prior * er;
    float sp    = __logf(1.0f + __expf(-fabsf(x))); // log1p(exp(-|x|))
    return fmaxf(x, 0.0f) - x * qt + sp;
}

// One CTA handles rows i=k and i=N-1-k of batch b: exactly N-1=2047 elements
// per block -> perfect load balance. adj/u rows are 16B-aligned -> 128-bit
// loads; q segment start is arbitrary mod 4 -> 4 scalar loads per quad.
__global__ __launch_bounds__(NTHR)
void loss_kernel(const int* __restrict__ adj, const int* __restrict__ t,
                 const float* __restrict__ u, const float* __restrict__ q,
                 float* __restrict__ out) {
    __shared__ Consts cs;
    __shared__ float  warp_sums[8];
    __shared__ bool   is_last;

    const int tid  = threadIdx.x;
    const int bidx = blockIdx.x;
    const int b    = bidx >> 10;        // / (N/2)
    const int k    = bidx & 1023;       // % (N/2)

    if (tid == 0) {
        int tb = t[b];
        double ft = 0.5 * (1.0 - pow(0.98, (double)(tb + 1)));          // Qt[t]
        int tm1 = (tb + TIMESTEPS - 1) % TIMESTEPS;                     // Qt[t-1], wraps
        double fp = 0.5 * (1.0 - pow(0.98, (double)(tm1 + 1)));
        cs.flip_t = (float)ft;          cs.omt    = (float)(1.0 - ft);
        cs.flip_p = (float)fp;          cs.omp    = (float)(1.0 - fp);
        cs.r_omt  = (float)(1.0 / (1.0 - ft));
        cs.r_flip = (float)(1.0 / ft);
    }
    __syncthreads();
    const Consts c = cs;

    float s = 0.0f;

    #pragma unroll
    for (int half = 0; half < 2; ++half) {
        const int i   = half ? (N - 1 - k) : k;
        const int len = i;                         // strict lower triangle: j in [0, i)
        if (len == 0) continue;

        const size_t rowoff = ((size_t)(b * N + i)) << 11;   // * N
        const int*   adj_row = adj + rowoff;
        const float* u_row   = u + rowoff;
        const float* q_row   = q + (size_t)b * (size_t)E + (((size_t)i * (i - 1)) >> 1);

        const int nv = len >> 2;
        for (int v = tid; v < nv; v += NTHR) {
            int4   A = reinterpret_cast<const int4*>(adj_row)[v];
            float4 U = reinterpret_cast<const float4*>(u_row)[v];
            int j = v << 2;
            float x0 = q_row[j + 0], x1 = q_row[j + 1];
            float x2 = q_row[j + 2], x3 = q_row[j + 3];
            s += term(A.x, U.x, x0, c);
            s += term(A.y, U.y, x1, c);
            s += term(A.z, U.z, x2, c);
            s += term(A.w, U.w, x3, c);
        }
        const int rem = len - (nv << 2);           // 0..3 tail elements
        if (tid < rem) {
            int j = (nv << 2) + tid;
            s += term(adj_row[j], u_row[j], q_row[j], c);
        }
    }

    // Block reduction
    #pragma unroll
    for (int off = 16; off; off >>= 1) s += __shfl_down_sync(0xffffffffu, s, off);
    const int lane = tid & 31, wid = tid >> 5;
    if (lane == 0) warp_sums[wid] = s;
    __syncthreads();
    if (wid == 0) {
        s = (lane < 8) ? warp_sums[lane] : 0.0f;
        #pragma unroll
        for (int off = 4; off; off >>= 1) s += __shfl_down_sync(0xffffffffu, s, off);
        if (lane == 0) g_partials[bidx] = s;
    }

    // Last-block-standing final reduction (counter wraps back to 0 -> replayable)
    __threadfence();
    if (tid == 0) {
        unsigned v = atomicInc(&g_count, NBLK - 1);
        is_last = (v == NBLK - 1);
    }
    __syncthreads();
    if (is_last) {
        float acc = 0.0f;
        for (int idx = tid; idx < NBLK; idx += NTHR) acc += g_partials[idx];
        #pragma unroll
        for (int off = 16; off; off >>= 1) acc += __shfl_down_sync(0xffffffffu, acc, off);
        if (lane == 0) warp_sums[wid] = acc;
        __syncthreads();
        if (wid == 0) {
            acc = (lane < 8) ? warp_sums[lane] : 0.0f;
            #pragma unroll
            for (int off = 4; off; off >>= 1) acc += __shfl_down_sync(0xffffffffu, acc, off);
            if (lane == 0) out[0] = acc * (1.0f / (float)(B * E));
        }
    }
}

extern "C" void kernel_launch(void* const* d_in, const int* in_sizes, int n_in,
                              void* d_out, int out_size) {
    // metadata order: adj_start (int32), t (int32), u (f32), q_approx (f32)
    const int*   adj = (const int*)d_in[0];
    const int*   t   = (const int*)d_in[1];
    const float* u   = (const float*)d_in[2];
    const float* q   = (const float*)d_in[3];
    float* out = (float*)d_out;

    loss_kernel<<<NBLK, NTHR>>>(adj, t, u, q, out);
}

// round 3
// speedup vs baseline: 2.7347x; 2.7347x over previous
#include <cuda_runtime.h>
#include <cuda_bf16.h>

constexpr int TIMESTEPS = 1000;
constexpr int B = 4;
constexpr int N = 2048;                                // power of two
constexpr long long E = (long long)N * (N - 1) / 2;    // 2,096,128
constexpr int NBLK = B * (N / 2);                      // 4096 blocks
constexpr int NTHR = 256;

// Cross-block reduction scratch. g_count self-resets (atomicInc wrap), so the
// kernel is graph-replay safe with no host-side zeroing.
__device__ float        g_partials[NBLK];
__device__ unsigned int g_count = 0;

struct Consts { float flip_t, omt, flip_p, omp, r_omt, r_flip; };

__device__ __forceinline__ float ex2(float x) {
    float r;
    asm("ex2.approx.f32 %0, %1;" : "=f"(r) : "f"(x));
    return r;
}
__device__ __forceinline__ float rcp(float x) {
    float r;
    asm("rcp.approx.f32 %0, %1;" : "=f"(r) : "f"(x));
    return r;
}

// Per-element loss term. Branch-free selects; no division; MUFU softplus.
__device__ __forceinline__ float term(int a, float uu, float x, const Consts& c) {
    bool  ab    = (a != 0);
    float pa    = ab ? c.omt : c.flip_t;       // Qt[t][a, 1]
    bool  x1    = uu < pa;                     // sampled bit
    float lik   = x1 ? 0.99f : 0.01f;          // Qt[0][x1, 1]
    float prior = ab ? c.omp : c.flip_p;       // Qt[t-1][a, 1]
    float er    = (ab == x1) ? c.r_omt : c.r_flip;  // 1 / Qt[t][a, x1]
    float qt    = lik * prior * er;
    float sp    = __logf(1.0f + __expf(-fabsf(x))); // log1p(exp(-|x|))
    return fmaxf(x, 0.0f) - x * qt + sp;
}

// One CTA handles rows i=k and i=N-1-k of batch b: exactly N-1=2047 elements
// per block. adj/u rows are 16B-aligned -> 128-bit loads; q segment start is
// arbitrary mod 4 -> scalar loads for q.
__global__ __launch_bounds__(NTHR)
void loss_kernel(const int* __restrict__ adj, const int* __restrict__ t,
                 const float* __restrict__ u, const float* __restrict__ q,
                 float* __restrict__ out) {
    __shared__ float warp_sums[8];
    __shared__ bool  is_last;

    const int tid  = threadIdx.x;
    const int bidx = blockIdx.x;
    const int b    = bidx >> 10;        // / (N/2)
    const int k    = bidx & 1023;       // % (N/2)

    // Per-thread fp32 constants (MUFU EX2/RCP) — no FP64, no barrier.
    Consts c;
    {
        const float L2_098 = -0.0291463173f;   // log2(0.98), rounded from double
        int tb = t[b];                         // L1-cached broadcast load
        float pt = ex2((float)(tb + 1) * L2_098);          // 0.98^(t+1)
        int tm1 = (tb + TIMESTEPS - 1) % TIMESTEPS;        // Qt[t-1] wraps at t=0
        float pp = ex2((float)(tm1 + 1) * L2_098);
        c.flip_t = 0.5f - 0.5f * pt;   c.omt = 0.5f + 0.5f * pt;
        c.flip_p = 0.5f - 0.5f * pp;   c.omp = 0.5f + 0.5f * pp;
        c.r_omt  = rcp(c.omt);
        c.r_flip = rcp(c.flip_t);
    }

    float s = 0.0f;

    #pragma unroll
    for (int half = 0; half < 2; ++half) {
        const int i   = half ? (N - 1 - k) : k;
        const int len = i;                         // strict lower triangle: j in [0, i)
        if (len == 0) continue;

        const size_t rowoff = ((size_t)(b * N + i)) << 11;   // * N
        const int*   adj_row = adj + rowoff;
        const float* u_row   = u + rowoff;
        const float* q_row   = q + (size_t)b * (size_t)E + (((size_t)i * (i - 1)) >> 1);

        const int nv = len >> 2;
        for (int v = tid; v < nv; v += NTHR) {
            int4   A = reinterpret_cast<const int4*>(adj_row)[v];
            float4 U = reinterpret_cast<const float4*>(u_row)[v];
            int j = v << 2;
            float x0 = q_row[j + 0], x1 = q_row[j + 1];
            float x2 = q_row[j + 2], x3 = q_row[j + 3];
            s += term(A.x, U.x, x0, c);
            s += term(A.y, U.y, x1, c);
            s += term(A.z, U.z, x2, c);
            s += term(A.w, U.w, x3, c);
        }
        const int rem = len - (nv << 2);           // 0..3 tail elements
        if (tid < rem) {
            int j = (nv << 2) + tid;
            s += term(adj_row[j], u_row[j], q_row[j], c);
        }
    }

    // Block reduction
    #pragma unroll
    for (int off = 16; off; off >>= 1) s += __shfl_down_sync(0xffffffffu, s, off);
    const int lane = tid & 31, wid = tid >> 5;
    if (lane == 0) warp_sums[wid] = s;
    __syncthreads();
    if (wid == 0) {
        s = (lane < 8) ? warp_sums[lane] : 0.0f;
        #pragma unroll
        for (int off = 4; off; off >>= 1) s += __shfl_down_sync(0xffffffffu, s, off);
        if (lane == 0) g_partials[bidx] = s;
    }

    // Last-block-standing final reduction (counter wraps to 0 -> replayable)
    __threadfence();
    if (tid == 0) {
        unsigned v = atomicInc(&g_count, NBLK - 1);
        is_last = (v == NBLK - 1);
    }
    __syncthreads();
    if (is_last) {
        float acc = 0.0f;
        for (int idx = tid; idx < NBLK; idx += NTHR) acc += g_partials[idx];
        #pragma unroll
        for (int off = 16; off; off >>= 1) acc += __shfl_down_sync(0xffffffffu, acc, off);
        if (lane == 0) warp_sums[wid] = acc;
        __syncthreads();
        if (wid == 0) {
            acc = (lane < 8) ? warp_sums[lane] : 0.0f;
            #pragma unroll
            for (int off = 4; off; off >>= 1) acc += __shfl_down_sync(0xffffffffu, acc, off);
            if (lane == 0) out[0] = acc * (1.0f / (float)(B * E));
        }
    }
}

extern "C" void kernel_launch(void* const* d_in, const int* in_sizes, int n_in,
                              void* d_out, int out_size) {
    // metadata order: adj_start (int32), t (int32), u (f32), q_approx (f32)
    const int*   adj = (const int*)d_in[0];
    const int*   t   = (const int*)d_in[1];
    const float* u   = (const float*)d_in[2];
    const float* q   = (const float*)d_in[3];
    float* out = (float*)d_out;

    loss_kernel<<<NBLK, NTHR>>>(adj, t, u, q, out);
}